// round 15
// baseline (speedup 1.0000x reference)
#include <cuda_runtime.h>
#include <cstddef>
#include <cstdint>

#define NB   4
#define TSZ  16
#define SRr  4
#define PD   1
#define SSn  11     // search span
#define SSC  9      // cropped span
#define WINs 26     // window size
#define WROW 28     // padded window row stride (112B = 16B-aligned rows)
#define SWt  0.1f
#define NMSE 176    // 11 sy * 16 rows

// ---------------- scratch (device globals; no allocation) ----------------
__device__ float g_ps1[NB*256*256], g_pd1[NB*256*256];
__device__ float g_ps2[NB*128*128], g_pd2[NB*128*128];
__device__ float g_ps3[NB*64*64],   g_pd3[NB*64*64];
__device__ float g_offA[NB*16*16*2];
__device__ float g_offB[NB*16*16*2];

// grid barrier + dynamic work counters
__device__ unsigned g_bar_count = 0;
__device__ unsigned g_bar_sense = 0;
__device__ unsigned g_work[4] = {0, 0, 0, 0};   // L3,L2,L1,L0 tile counters

// ---------------- shared memory -------------------------------------------
struct StepSh {
    float src[2][TSZ*TSZ];
    float win[2][WINs*WROW];
    float part[2][SSn*SSn*17];
    float dist[SSn*SSn];
    float res[3];
    unsigned claim[2];
};
struct PyrSh { float a[92*45]; float b[44*45]; };
union ShMem { StepSh st; PyrSh py; };

__device__ __forceinline__ unsigned long long umin64(unsigned long long a, unsigned long long b)
{ return a < b ? a : b; }

// ---------------- cp.async helpers -----------------------------------------
__device__ __forceinline__ void cp_async4(void* smem, const void* g)
{
    unsigned sa = (unsigned)__cvta_generic_to_shared(smem);
    asm volatile("cp.async.ca.shared.global [%0], [%1], 4;" :: "r"(sa), "l"(g));
}
__device__ __forceinline__ void cp_commit()
{ asm volatile("cp.async.commit_group;"); }
template<int N> __device__ __forceinline__ void cp_wait()
{ asm volatile("cp.async.wait_group %0;" :: "n"(N)); }

// ---------------- grid barrier (all blocks co-resident) --------------------
// releasing thread resets the given counters inside the serialization point.
__device__ __forceinline__ void grid_barrier(int G, unsigned& ls, unsigned* rst0, unsigned* rst1)
{
    __syncthreads();
    if (threadIdx.x == 0) {
        ls ^= 1u;
        __threadfence();
        unsigned v = atomicAdd(&g_bar_count, 1u);
        if (v == (unsigned)(G - 1)) {
            if (rst0) *rst0 = 0u;
            if (rst1) *rst1 = 0u;
            g_bar_count = 0;
            __threadfence();
            *(volatile unsigned*)&g_bar_sense = ls;
        } else {
            while (*(volatile unsigned*)&g_bar_sense != ls)
                __nanosleep(64);
            __threadfence();
        }
    }
    __syncthreads();
}

// ---------------- pyramid: one 8x8 L3 tile of one image --------------------
__device__ void pyr_block(PyrSh& sh, int vb,
                          const float* __restrict__ src, const float* __restrict__ dst)
{
    const int im = vb >> 6;
    const int t  = vb & 63;
    const int bi = t >> 3, bj = t & 7;
    const int tid = threadIdx.x;

    const float* in = (im < NB) ? (src + (size_t)im * 512 * 512)
                                : (dst + (size_t)(im - NB) * 512 * 512);
    float* o1 = (im < NB) ? (g_ps1 + (size_t)im * 256 * 256) : (g_pd1 + (size_t)(im-NB) * 256 * 256);
    float* o2 = (im < NB) ? (g_ps2 + (size_t)im * 128 * 128) : (g_pd2 + (size_t)(im-NB) * 128 * 128);
    float* o3 = (im < NB) ? (g_ps3 + (size_t)im *  64 *  64) : (g_pd3 + (size_t)(im-NB) *  64 *  64);

    // separable taps: fused blur(5x5,zero-pad)+avgpool(2) = 6-tap outer product
    const float g0 = expf(-2.0f), g1 = expf(-0.5f), g2 = 1.0f;
    const float S  = g2 + 2.f*g1 + 2.f*g0;
    float ww[6];
    {
        const float ga[5] = {g0, g1, g2, g1, g0};
        ww[0] = 0.5f * ga[0] / S;
        #pragma unroll
        for (int u = 1; u < 5; u++) ww[u] = 0.5f * (ga[u] + ga[u-1]) / S;
        ww[5] = 0.5f * ga[4] / S;
    }

    const int yb = 64*bi - 14;
    const int xb = 64*bj - 14;

    // pass 1h: input -> tmp (92 x 44); interior fast path
    if (bi >= 1 && bi <= 6 && bj >= 1 && bj <= 6) {
        for (int id = tid; id < 92*44; id += 256) {
            int yy = id / 44, cx = id - yy*44;
            const float* row = in + (size_t)(yb + yy) * 512 + (xb + 2*cx);
            float v = 0.f;
            #pragma unroll
            for (int k = 0; k < 6; k++) v = fmaf(ww[k], row[k], v);
            sh.a[yy*45 + cx] = v;
        }
    } else {
        for (int id = tid; id < 92*44; id += 256) {
            int yy = id / 44, cx = id - yy*44;
            int gy = yb + yy;
            float v = 0.f;
            if (gy >= 0 && gy < 512) {
                const float* row = in + (size_t)gy * 512;
                int gx = xb + 2*cx;
                #pragma unroll
                for (int k = 0; k < 6; k++) {
                    int xx = gx + k;
                    if (xx >= 0 && xx < 512) v = fmaf(ww[k], row[xx], v);
                }
            }
            sh.a[yy*45 + cx] = v;
        }
    }
    __syncthreads();

    // pass 1v: -> level1 (44x44), write owned 32x32
    for (int id = tid; id < 44*44; id += 256) {
        int cy = id / 44, cx = id - cy*44;
        float v = 0.f;
        #pragma unroll
        for (int k = 0; k < 6; k++) v = fmaf(ww[k], sh.a[(2*cy + k)*45 + cx], v);
        int r1 = 32*bi - 6 + cy, c1 = 32*bj - 6 + cx;
        bool inimg = (r1 >= 0 && r1 < 256 && c1 >= 0 && c1 < 256);
        sh.b[cy*45 + cx] = inimg ? v : 0.f;
        if (cy >= 6 && cy < 38 && cx >= 6 && cx < 38)
            o1[(size_t)r1 * 256 + c1] = v;
    }
    __syncthreads();

    // pass 2h
    for (int id = tid; id < 44*20; id += 256) {
        int yy = id / 20, cx = id - yy*20;
        float v = 0.f;
        #pragma unroll
        for (int k = 0; k < 6; k++) v = fmaf(ww[k], sh.b[yy*45 + 2*cx + k], v);
        sh.a[yy*21 + cx] = v;
    }
    __syncthreads();

    // pass 2v: -> level2 (20x20), write owned 16x16
    for (int id = tid; id < 20*20; id += 256) {
        int cy = id / 20, cx = id - cy*20;
        float v = 0.f;
        #pragma unroll
        for (int k = 0; k < 6; k++) v = fmaf(ww[k], sh.a[(2*cy + k)*21 + cx], v);
        int r2 = 16*bi - 2 + cy, c2 = 16*bj - 2 + cx;
        bool inimg = (r2 >= 0 && r2 < 128 && c2 >= 0 && c2 < 128);
        sh.b[cy*21 + cx] = inimg ? v : 0.f;
        if (cy >= 2 && cy < 18 && cx >= 2 && cx < 18)
            o2[(size_t)r2 * 128 + c2] = v;
    }
    __syncthreads();

    // pass 3h
    for (int id = tid; id < 20*8; id += 256) {
        int yy = id >> 3, cx = id & 7;
        float v = 0.f;
        #pragma unroll
        for (int k = 0; k < 6; k++) v = fmaf(ww[k], sh.b[yy*21 + 2*cx + k], v);
        sh.a[yy*9 + cx] = v;
    }
    __syncthreads();

    // pass 3v: -> level3 (8x8)
    for (int id = tid; id < 64; id += 256) {
        int cy = id >> 3, cx = id & 7;
        float v = 0.f;
        #pragma unroll
        for (int k = 0; k < 6; k++) v = fmaf(ww[k], sh.a[(2*cy + k)*9 + cx], v);
        o3[(size_t)(8*bi + cy) * 64 + (8*bj + cx)] = v;
    }
    __syncthreads();
}

// ---------------- step helpers ---------------------------------------------
__device__ __forceinline__ void inherit_off(int nb, int ty, int tx, int H,
                                            const float* __restrict__ prev_off, int pnthLog,
                                            float& iyf, float& ixf)
{
    iyf = 0.f; ixf = 0.f;
    if (prev_off) {
        int pidx = (((nb << pnthLog) + (ty >> 1)) << pnthLog) + (tx >> 1);
        const float* p = prev_off + 2*(size_t)pidx;
        float iy = (float)(ty*TSZ), ix = (float)(tx*TSZ);
        iyf = rintf(fminf(fmaxf(2.f*p[0] + iy, 0.f), (float)(H-TSZ)) - iy);
        ixf = rintf(fminf(fmaxf(2.f*p[1] + ix, 0.f), (float)(H-TSZ)) - ix);
    }
}

// issue cp.async for one tile's window + src tile into buffer `buf`.
__device__ void issue_load(StepSh& sh, int buf, int tile,
                           const float* __restrict__ src, const float* __restrict__ dst,
                           int H, int nthLog, const float* __restrict__ prev_off, int pnthLog)
{
    const int tid = threadIdx.x;
    const int w = tid >> 5, lane = tid & 31;
    const int msk = (1 << nthLog) - 1;
    const int tx = tile & msk, ty = (tile >> nthLog) & msk, nb = tile >> (2*nthLog);
    float iyf, ixf; inherit_off(nb, ty, tx, H, prev_off, pnthLog, iyf, ixf);
    const float* simg = src + (size_t)nb * H * H;
    const float* dimg = dst + (size_t)nb * H * H;
    const int y0 = ty*TSZ + (int)iyf - (SRr + PD);
    const int x0 = tx*TSZ + (int)ixf - (SRr + PD);

    if (lane < WINs) {
        if (y0 >= 0 && x0 >= 0 && y0 + WINs <= H && x0 + WINs <= H) {
            const float* base = dimg + (size_t)y0 * H + x0 + lane;
            #pragma unroll
            for (int rr = 0; rr < 4; rr++) {
                int r = w + 8*rr;
                if (r < WINs) cp_async4(&sh.win[buf][r*WROW + lane], base + (size_t)r * H);
            }
        } else {
            int xx = min(max(x0 + lane, 0), H - 1);
            #pragma unroll
            for (int rr = 0; rr < 4; rr++) {
                int r = w + 8*rr;
                if (r < WINs) {
                    int yy = min(max(y0 + r, 0), H - 1);
                    cp_async4(&sh.win[buf][r*WROW + lane], dimg + (size_t)yy * H + xx);
                }
            }
        }
    }
    {
        int i = tid >> 4, j = tid & 15;
        cp_async4(&sh.src[buf][tid], simg + (size_t)(ty*TSZ + i) * H + tx*TSZ + j);
    }
}

// MSE partials, threads 0..175: (sy,i); window row + src row in registers
__device__ __forceinline__ void mse_tile(StepSh& sh, int pb)
{
    const int tid = threadIdx.x;
    const int sy = tid >> 4, i = tid & 15;
    float s[16], w[WINs];
    const float4* s4 = reinterpret_cast<const float4*>(&sh.src[pb][i*TSZ]);
    #pragma unroll
    for (int j4 = 0; j4 < 4; j4++) {
        float4 v = s4[j4];
        s[4*j4] = v.x; s[4*j4+1] = v.y; s[4*j4+2] = v.z; s[4*j4+3] = v.w;
    }
    const float* wr = &sh.win[pb][(sy + i)*WROW];
    const float4* w4 = reinterpret_cast<const float4*>(wr);
    #pragma unroll
    for (int j4 = 0; j4 < 6; j4++) {
        float4 v = w4[j4];
        w[4*j4] = v.x; w[4*j4+1] = v.y; w[4*j4+2] = v.z; w[4*j4+3] = v.w;
    }
    w[24] = wr[24]; w[25] = wr[25];
    float* pp = &sh.part[pb][sy*SSn*17 + i];
    #pragma unroll
    for (int sx = 0; sx < SSn; sx++) {
        float a0 = 0.f, a1 = 0.f;
        #pragma unroll
        for (int j = 0; j < 16; j += 2) {
            float d0 = w[sx + j]     - s[j];     a0 = fmaf(d0, d0, a0);
            float d1 = w[sx + j + 1] - s[j + 1]; a1 = fmaf(d1, d1, a1);
        }
        pp[sx*17] = a0 + a1;
    }
}

// reduce 16 partials for candidate c (same tree as before)
__device__ __forceinline__ float reduce_cand(const float* __restrict__ p, int c)
{
    const float* q = p + c*17;
    float q0 = (q[0] + q[1])   + (q[2] + q[3]);
    float q1 = (q[4] + q[5])   + (q[6] + q[7]);
    float q2 = (q[8] + q[9])   + (q[10] + q[11]);
    float q3 = (q[12] + q[13]) + (q[14] + q[15]);
    float sum = (q0 + q1) + (q2 + q3);
    int sy = c / SSn, sx = c - (c/SSn)*SSn;
    float ay = ((float)sy - (float)(SRr+PD)) / (float)SSn;
    float ax = ((float)sx - (float)(SRr+PD)) / (float)SSn;
    return sum * (1.0f/256.0f) + SWt * (ay*ay + ax*ax);
}

// warp argmin over 81 cropped candidates (first-index tie-break); valid on lane 0
__device__ __forceinline__ unsigned long long argmin81(const float* __restrict__ dist, int lane)
{
    unsigned long long key = ~0ULL;
    for (int k = lane; k < SSC*SSC; k += 32) {
        int py = k / SSC, px = k - (k/SSC)*SSC;
        float v = dist[(py+PD)*SSn + px + PD];
        key = umin64(key, ((unsigned long long)__float_as_uint(v) << 32) | (unsigned)k);
    }
    #pragma unroll
    for (int o = 16; o > 0; o >>= 1)
        key = umin64(key, __shfl_down_sync(0xffffffffu, key, o));
    return key;
}

// subpixel refine from argmin key; writes out_off + sh.res. One thread.
__device__ __forceinline__ void refine_store(StepSh& sh, unsigned long long key,
                                             int nb, int ty, int tx, int H, int tile,
                                             const float* __restrict__ prev_off, int pnthLog,
                                             float* __restrict__ out_off)
{
    int bk = (int)(key & 0xffffffffu);
    float best = __uint_as_float((unsigned)(key >> 32));
    int py = bk / SSC, px = bk - (bk/SSC)*SSC;
    float r[9];
    #pragma unroll
    for (int dy = 0; dy < 3; dy++)
        #pragma unroll
        for (int dx = 0; dx < 3; dx++)
            r[dy*3+dx] = sh.dist[(py+PD-1+dy)*SSn + (px+PD-1+dx)];

    float a11 = (  r[0]-2.f*r[1]+r[2] + 2.f*r[3]-4.f*r[4]+2.f*r[5] +   r[6]-2.f*r[7]+r[8]) * 0.25f;
    float a22 = (  r[0]+2.f*r[1]+r[2] - 2.f*r[3]-4.f*r[4]-2.f*r[5] +   r[6]+2.f*r[7]+r[8]) * 0.25f;
    float a12 = (  r[0]        -r[2]                               -   r[6]         +r[8]) * 0.25f;
    float b1  = ( -r[0]        +r[2] - 2.f*r[3]        +2.f*r[5]   -   r[6]         +r[8]) * 0.125f;
    float b2  = ( -r[0]-2.f*r[1]-r[2]                              +   r[6]+2.f*r[7]+r[8]) * 0.125f;
    a11 = fmaxf(a11, 0.f);
    a22 = fmaxf(a22, 0.f);
    float det  = a11*a22 - a12*a12;
    float a12z = (det < 0.f) ? 0.f : a12;
    float mux  = -(a22*b1 - a12z*b2) / det;
    float muy  = -(a11*b2 - a12z*b1) / det;
    float mlen = sqrtf(muy*muy + mux*mux);
    float dxs  = (mlen < 1.f) ? mux : 0.f;   // NaN/Inf -> 0, matches jnp.where
    float dys  = (mlen < 1.f) ? muy : 0.f;

    float iyf, ixf; inherit_off(nb, ty, tx, H, prev_off, pnthLog, iyf, ixf);
    float offy = iyf + (float)(py - SRr) + dys;
    float offx = ixf + (float)(px - SRr) + dxs;
    if (out_off) { out_off[2*(size_t)tile] = offy; out_off[2*(size_t)tile + 1] = offx; }
    sh.res[0] = offy; sh.res[1] = offx; sh.res[2] = best;
}

// post on warps 6,7 only (64 threads) — runs concurrently with MSE.
__device__ void post2(StepSh& sh, int pb, int tile, int H, int nthLog,
                      const float* __restrict__ prev_off, int pnthLog,
                      float* __restrict__ out_off, float* __restrict__ out_pix)
{
    const int wtid = threadIdx.x - 192;
    #pragma unroll
    for (int c = wtid; c < SSn*SSn; c += 64)
        sh.dist[c] = reduce_cand(sh.part[pb], c);
    asm volatile("bar.sync 1, 64;" ::: "memory");

    const int msk = (1 << nthLog) - 1;
    const int tx = tile & msk, ty = (tile >> nthLog) & msk, nb = tile >> (2*nthLog);
    if (wtid < 32) {
        unsigned long long key = argmin81(sh.dist, wtid);
        if (wtid == 0)
            refine_store(sh, key, nb, ty, tx, H, tile, prev_off, pnthLog, out_off);
    }
    if (out_pix) {
        asm volatile("bar.sync 1, 64;" ::: "memory");
        float2 ov = make_float2(sh.res[0], sh.res[1]);
        float dv = sh.res[2];
        #pragma unroll
        for (int k = 0; k < 4; k++) {
            int px = wtid + 64*k;
            int i = px >> 4, j = px & 15;
            int y = ty*TSZ + i, x = tx*TSZ + j;
            size_t pix = ((size_t)nb * H + y) * H + x;
            reinterpret_cast<float2*>(out_pix)[pix] = ov;
            out_pix[(size_t)NB * H * H * 2 + pix] = dv;
        }
    }
}

// full-block post (epilogue, last tile of a level)
__device__ void post_full(StepSh& sh, int pb, int tile, int H, int nthLog,
                          const float* __restrict__ prev_off, int pnthLog,
                          float* __restrict__ out_off, float* __restrict__ out_pix)
{
    const int tid = threadIdx.x;
    if (tid < SSn*SSn)
        sh.dist[tid] = reduce_cand(sh.part[pb], tid);
    __syncthreads();
    const int msk = (1 << nthLog) - 1;
    const int tx = tile & msk, ty = (tile >> nthLog) & msk, nb = tile >> (2*nthLog);
    if (tid < 32) {
        unsigned long long key = argmin81(sh.dist, tid);
        if (tid == 0)
            refine_store(sh, key, nb, ty, tx, H, tile, prev_off, pnthLog, out_off);
    }
    if (out_pix) {
        __syncthreads();
        float2 ov = make_float2(sh.res[0], sh.res[1]);
        int i = tid >> 4, j = tid & 15;
        int y = ty*TSZ + i, x = tx*TSZ + j;
        size_t pix = ((size_t)nb * H + y) * H + x;
        reinterpret_cast<float2*>(out_pix)[pix] = ov;
        out_pix[(size_t)NB * H * H * 2 + pix] = sh.res[2];
    }
}

// one alignment level: dynamic tiles, cp.async prefetch, post overlapped on warps 6-7
__device__ void step_level(StepSh& sh, int n,
                           const float* __restrict__ src, const float* __restrict__ dst,
                           int H, int nthLog,
                           const float* __restrict__ prev_off, int pnthLog,
                           float* __restrict__ out_off, float* __restrict__ out_pix,
                           unsigned* ctr)
{
    const int tid = threadIdx.x;
    if (tid == 0) {
        sh.claim[0] = atomicAdd(ctr, 1u);
        sh.claim[1] = atomicAdd(ctr, 1u);
    }
    __syncthreads();
    int cur = (int)sh.claim[0], nxt = (int)sh.claim[1];
    __syncthreads();                 // claims consumed before loop overwrites
    if (cur >= n) return;

    issue_load(sh, 0, cur, src, dst, H, nthLog, prev_off, pnthLog);
    cp_commit();
    bool nxt_valid = (nxt < n);
    if (nxt_valid) {
        issue_load(sh, 1, nxt, src, dst, H, nthLog, prev_off, pnthLog);
        cp_commit();
    }
    int prev = -1, pb = 0;
    for (;;) {
        if (nxt_valid) cp_wait<1>(); else cp_wait<0>();
        __syncthreads();             // A: win/src[pb] visible; part[pb] free
        if (tid == 0) sh.claim[0] = atomicAdd(ctr, 1u);
        if (tid < NMSE)
            mse_tile(sh, pb);
        else if (tid >= 192 && prev >= 0)
            post2(sh, pb ^ 1, prev, H, nthLog, prev_off, pnthLog, out_off, out_pix);
        __syncthreads();             // B: part[pb] ready; post done; claim visible
        prev = cur;
        if (!nxt_valid) break;
        cur = nxt;
        int nn = (int)sh.claim[0];
        pb ^= 1;                     // cur now sits in buffer pb
        nxt_valid = (nn < n);
        if (nxt_valid) {
            nxt = nn;
            issue_load(sh, pb ^ 1, nn, src, dst, H, nthLog, prev_off, pnthLog);
            cp_commit();
        }
    }
    // epilogue: post the final tile with the whole block
    post_full(sh, pb, prev, H, nthLog, prev_off, pnthLog, out_off, out_pix);
}

// ---------------- persistent mega-kernel ------------------------------------
__global__ void __launch_bounds__(256)
align_kernel(const float* __restrict__ src, const float* __restrict__ dst,
             float* __restrict__ out, int G)
{
    __shared__ ShMem sh;
    unsigned ls = *(volatile unsigned*)&g_bar_sense;   // robust to any barrier parity

    for (int vb = blockIdx.x; vb < 8*64; vb += G)
        pyr_block(sh.py, vb, src, dst);
    grid_barrier(G, ls, &g_work[3], nullptr);          // clean L0 residue (prev launch)

    step_level(sh.st, NB*4*4,   g_ps3, g_pd3,  64, 2, nullptr, 0, g_offA, nullptr, &g_work[0]);
    grid_barrier(G, ls, &g_work[0], nullptr);

    step_level(sh.st, NB*8*8,   g_ps2, g_pd2, 128, 3, g_offA,  2, g_offB, nullptr, &g_work[1]);
    grid_barrier(G, ls, &g_work[1], nullptr);

    step_level(sh.st, NB*16*16, g_ps1, g_pd1, 256, 4, g_offB,  3, g_offA, nullptr, &g_work[2]);
    grid_barrier(G, ls, &g_work[2], nullptr);

    step_level(sh.st, NB*32*32, src,   dst,   512, 5, g_offA,  4, nullptr, out,    &g_work[3]);
}

// ---------------- launch ---------------------------------------------------
extern "C" void kernel_launch(void* const* d_in, const int* in_sizes, int n_in,
                              void* d_out, int out_size)
{
    const float* src = (const float*)d_in[0];
    const float* dst = (const float*)d_in[1];
    float* out = (float*)d_out;

    static int G = 0;
    if (G == 0) {
        int nsm = 0, bpm = 0;
        cudaDeviceGetAttribute(&nsm, cudaDevAttrMultiProcessorCount, 0);
        cudaOccupancyMaxActiveBlocksPerMultiprocessor(&bpm, align_kernel, 256, 0);
        if (bpm < 1) bpm = 1;
        G = nsm * bpm;
    }

    align_kernel<<<G, 256>>>(src, dst, out, G);
}

// round 16
// speedup vs baseline: 1.3276x; 1.3276x over previous
#include <cuda_runtime.h>
#include <cstddef>
#include <cstdint>

#define NB   4
#define TSZ  16
#define SRr  4
#define PD   1
#define SSn  11     // search span
#define SSC  9      // cropped span
#define WINs 26     // window size
#define WROW 28     // padded window row stride (112B, 16B-aligned rows)
#define SWt  0.1f
#define NMSE 176    // 11 sy * 16 rows

// ---------------- scratch (device globals; no allocation) ----------------
__device__ float g_ps1[NB*256*256], g_pd1[NB*256*256];
__device__ float g_ps2[NB*128*128], g_pd2[NB*128*128];
__device__ float g_ps3[NB*64*64],   g_pd3[NB*64*64];
__device__ float g_offA[NB*16*16*2];
__device__ float g_offB[NB*16*16*2];

// grid barrier (sense-reversal; even # barriers/launch -> replay-clean)
__device__ unsigned g_bar_count = 0;
__device__ unsigned g_bar_sense = 0;

// ---------------- shared memory -------------------------------------------
struct StepSh {
    float src[2][TSZ*TSZ];
    float win[2][WINs*WROW];
    float init[2][2];
    float part[SSn*SSn*17];
    float dist[SSn*SSn];
    float res[3];
};
struct PyrSh { float a[92*45]; float b[44*45]; };
union ShMem { StepSh st; PyrSh py; };

__device__ __forceinline__ unsigned long long umin64(unsigned long long a, unsigned long long b)
{ return a < b ? a : b; }

// ---------------- cp.async helpers -----------------------------------------
__device__ __forceinline__ void cp_async4(void* smem, const void* g)
{
    unsigned sa = (unsigned)__cvta_generic_to_shared(smem);
    asm volatile("cp.async.ca.shared.global [%0], [%1], 4;" :: "r"(sa), "l"(g));
}
__device__ __forceinline__ void cp_commit()
{ asm volatile("cp.async.commit_group;"); }
template<int N> __device__ __forceinline__ void cp_wait()
{ asm volatile("cp.async.wait_group %0;" :: "n"(N)); }

// ---------------- grid barrier (all blocks co-resident) --------------------
__device__ __forceinline__ void grid_barrier(int G, unsigned& local_sense)
{
    __syncthreads();
    if (threadIdx.x == 0) {
        local_sense ^= 1u;
        __threadfence();
        unsigned v = atomicAdd(&g_bar_count, 1u);
        if (v == (unsigned)(G - 1)) {
            g_bar_count = 0;
            __threadfence();
            *(volatile unsigned*)&g_bar_sense = local_sense;
        } else {
            while (*(volatile unsigned*)&g_bar_sense != local_sense)
                __nanosleep(64);
            __threadfence();
        }
    }
    __syncthreads();
}

// ---------------- pyramid: one 8x8 L3 tile of one image --------------------
__device__ void pyr_block(PyrSh& sh, int vb,
                          const float* __restrict__ src, const float* __restrict__ dst)
{
    const int im = vb >> 6;
    const int t  = vb & 63;
    const int bi = t >> 3, bj = t & 7;
    const int tid = threadIdx.x;

    const float* in = (im < NB) ? (src + (size_t)im * 512 * 512)
                                : (dst + (size_t)(im - NB) * 512 * 512);
    float* o1 = (im < NB) ? (g_ps1 + (size_t)im * 256 * 256) : (g_pd1 + (size_t)(im-NB) * 256 * 256);
    float* o2 = (im < NB) ? (g_ps2 + (size_t)im * 128 * 128) : (g_pd2 + (size_t)(im-NB) * 128 * 128);
    float* o3 = (im < NB) ? (g_ps3 + (size_t)im *  64 *  64) : (g_pd3 + (size_t)(im-NB) *  64 *  64);

    // separable taps: fused blur(5x5,zero-pad)+avgpool(2) = 6-tap outer product
    const float g0 = expf(-2.0f), g1 = expf(-0.5f), g2 = 1.0f;
    const float S  = g2 + 2.f*g1 + 2.f*g0;
    float ww[6];
    {
        const float ga[5] = {g0, g1, g2, g1, g0};
        ww[0] = 0.5f * ga[0] / S;
        #pragma unroll
        for (int u = 1; u < 5; u++) ww[u] = 0.5f * (ga[u] + ga[u-1]) / S;
        ww[5] = 0.5f * ga[4] / S;
    }

    const int yb = 64*bi - 14;
    const int xb = 64*bj - 14;

    // pass 1h: input -> tmp (92 x 44); interior fast path
    if (bi >= 1 && bi <= 6 && bj >= 1 && bj <= 6) {
        for (int id = tid; id < 92*44; id += 256) {
            int yy = id / 44, cx = id - yy*44;
            const float* row = in + (size_t)(yb + yy) * 512 + (xb + 2*cx);
            float v = 0.f;
            #pragma unroll
            for (int k = 0; k < 6; k++) v = fmaf(ww[k], row[k], v);
            sh.a[yy*45 + cx] = v;
        }
    } else {
        for (int id = tid; id < 92*44; id += 256) {
            int yy = id / 44, cx = id - yy*44;
            int gy = yb + yy;
            float v = 0.f;
            if (gy >= 0 && gy < 512) {
                const float* row = in + (size_t)gy * 512;
                int gx = xb + 2*cx;
                #pragma unroll
                for (int k = 0; k < 6; k++) {
                    int xx = gx + k;
                    if (xx >= 0 && xx < 512) v = fmaf(ww[k], row[xx], v);
                }
            }
            sh.a[yy*45 + cx] = v;
        }
    }
    __syncthreads();

    // pass 1v: -> level1 (44x44), write owned 32x32
    for (int id = tid; id < 44*44; id += 256) {
        int cy = id / 44, cx = id - cy*44;
        float v = 0.f;
        #pragma unroll
        for (int k = 0; k < 6; k++) v = fmaf(ww[k], sh.a[(2*cy + k)*45 + cx], v);
        int r1 = 32*bi - 6 + cy, c1 = 32*bj - 6 + cx;
        bool inimg = (r1 >= 0 && r1 < 256 && c1 >= 0 && c1 < 256);
        sh.b[cy*45 + cx] = inimg ? v : 0.f;
        if (cy >= 6 && cy < 38 && cx >= 6 && cx < 38)
            o1[(size_t)r1 * 256 + c1] = v;
    }
    __syncthreads();

    // pass 2h
    for (int id = tid; id < 44*20; id += 256) {
        int yy = id / 20, cx = id - yy*20;
        float v = 0.f;
        #pragma unroll
        for (int k = 0; k < 6; k++) v = fmaf(ww[k], sh.b[yy*45 + 2*cx + k], v);
        sh.a[yy*21 + cx] = v;
    }
    __syncthreads();

    // pass 2v: -> level2 (20x20), write owned 16x16
    for (int id = tid; id < 20*20; id += 256) {
        int cy = id / 20, cx = id - cy*20;
        float v = 0.f;
        #pragma unroll
        for (int k = 0; k < 6; k++) v = fmaf(ww[k], sh.a[(2*cy + k)*21 + cx], v);
        int r2 = 16*bi - 2 + cy, c2 = 16*bj - 2 + cx;
        bool inimg = (r2 >= 0 && r2 < 128 && c2 >= 0 && c2 < 128);
        sh.b[cy*21 + cx] = inimg ? v : 0.f;
        if (cy >= 2 && cy < 18 && cx >= 2 && cx < 18)
            o2[(size_t)r2 * 128 + c2] = v;
    }
    __syncthreads();

    // pass 3h
    for (int id = tid; id < 20*8; id += 256) {
        int yy = id >> 3, cx = id & 7;
        float v = 0.f;
        #pragma unroll
        for (int k = 0; k < 6; k++) v = fmaf(ww[k], sh.b[yy*21 + 2*cx + k], v);
        sh.a[yy*9 + cx] = v;
    }
    __syncthreads();

    // pass 3v: -> level3 (8x8)
    for (int id = tid; id < 64; id += 256) {
        int cy = id >> 3, cx = id & 7;
        float v = 0.f;
        #pragma unroll
        for (int k = 0; k < 6; k++) v = fmaf(ww[k], sh.a[(2*cy + k)*9 + cx], v);
        o3[(size_t)(8*bi + cy) * 64 + (8*bj + cx)] = v;
    }
    __syncthreads();
}

// ---------------- step helpers ---------------------------------------------
__device__ __forceinline__ void inherit_off(int nb, int ty, int tx, int H,
                                            const float* __restrict__ prev_off, int pnthLog,
                                            float& iyf, float& ixf)
{
    iyf = 0.f; ixf = 0.f;
    if (prev_off) {
        int pidx = (((nb << pnthLog) + (ty >> 1)) << pnthLog) + (tx >> 1);
        const float* p = prev_off + 2*(size_t)pidx;
        float iy = (float)(ty*TSZ), ix = (float)(tx*TSZ);
        iyf = rintf(fminf(fmaxf(2.f*p[0] + iy, 0.f), (float)(H-TSZ)) - iy);
        ixf = rintf(fminf(fmaxf(2.f*p[1] + ix, 0.f), (float)(H-TSZ)) - ix);
    }
}

// issue async copies for one tile's window + src tile into buffer `buf`.
// All 256 threads; ~4 LDGSTS each; returns immediately (no stall).
__device__ void issue_load(StepSh& sh, int buf, int tile,
                           const float* __restrict__ src, const float* __restrict__ dst,
                           int H, int nthLog, const float* __restrict__ prev_off, int pnthLog)
{
    const int tid = threadIdx.x;
    const int w = tid >> 5, lane = tid & 31;
    const int msk = (1 << nthLog) - 1;
    const int tx = tile & msk, ty = (tile >> nthLog) & msk, nb = tile >> (2*nthLog);
    float iyf, ixf; inherit_off(nb, ty, tx, H, prev_off, pnthLog, iyf, ixf);
    const float* simg = src + (size_t)nb * H * H;
    const float* dimg = dst + (size_t)nb * H * H;
    const int y0 = ty*TSZ + (int)iyf - (SRr + PD);
    const int x0 = tx*TSZ + (int)ixf - (SRr + PD);

    if (lane < WINs) {
        if (y0 >= 0 && x0 >= 0 && y0 + WINs <= H && x0 + WINs <= H) {
            const float* base = dimg + (size_t)y0 * H + x0 + lane;
            #pragma unroll
            for (int rr = 0; rr < 4; rr++) {
                int r = w + 8*rr;
                if (r < WINs) cp_async4(&sh.win[buf][r*WROW + lane], base + (size_t)r * H);
            }
        } else {
            int xx = min(max(x0 + lane, 0), H - 1);
            #pragma unroll
            for (int rr = 0; rr < 4; rr++) {
                int r = w + 8*rr;
                if (r < WINs) {
                    int yy = min(max(y0 + r, 0), H - 1);
                    cp_async4(&sh.win[buf][r*WROW + lane], dimg + (size_t)yy * H + xx);
                }
            }
        }
    }
    {
        int i = tid >> 4, j = tid & 15;
        cp_async4(&sh.src[buf][tid], simg + (size_t)(ty*TSZ + i) * H + tx*TSZ + j);
    }
    if (tid == 0) { sh.init[buf][0] = iyf; sh.init[buf][1] = ixf; }
}

// MSE partials, threads 0..175: (sy,i); window row + src row in registers
// register fill via LDS.128 (rows are 16B-aligned with WROW=28)
__device__ __forceinline__ void mse_tile(StepSh& sh, int buf)
{
    const int tid = threadIdx.x;
    const int sy = tid >> 4, i = tid & 15;
    float s[16], w[WINs];
    const float4* s4 = reinterpret_cast<const float4*>(&sh.src[buf][i*TSZ]);
    #pragma unroll
    for (int j4 = 0; j4 < 4; j4++) {
        float4 v = s4[j4];
        s[4*j4] = v.x; s[4*j4+1] = v.y; s[4*j4+2] = v.z; s[4*j4+3] = v.w;
    }
    const float* wr = &sh.win[buf][(sy + i)*WROW];
    const float4* w4 = reinterpret_cast<const float4*>(wr);
    #pragma unroll
    for (int j4 = 0; j4 < 6; j4++) {
        float4 v = w4[j4];
        w[4*j4] = v.x; w[4*j4+1] = v.y; w[4*j4+2] = v.z; w[4*j4+3] = v.w;
    }
    w[24] = wr[24]; w[25] = wr[25];
    float* pp = &sh.part[sy*SSn*17 + i];
    #pragma unroll
    for (int sx = 0; sx < SSn; sx++) {
        float a0 = 0.f, a1 = 0.f;
        #pragma unroll
        for (int j = 0; j < 16; j += 2) {
            float d0 = w[sx + j]     - s[j];     a0 = fmaf(d0, d0, a0);
            float d1 = w[sx + j + 1] - s[j + 1]; a1 = fmaf(d1, d1, a1);
        }
        pp[sx*17] = a0 + a1;
    }
}

// reduce + argmin + subpixel. All threads enter (internal barrier).
__device__ void post_tile(StepSh& sh, int buf, float* out_off)
{
    const int tid = threadIdx.x;
    if (tid < SSn*SSn) {
        const float* p = &sh.part[tid*17];
        float q0 = (p[0] + p[1])   + (p[2] + p[3]);
        float q1 = (p[4] + p[5])   + (p[6] + p[7]);
        float q2 = (p[8] + p[9])   + (p[10] + p[11]);
        float q3 = (p[12] + p[13]) + (p[14] + p[15]);
        float sum = (q0 + q1) + (q2 + q3);
        int sy = tid / SSn, sx = tid - (tid/SSn)*SSn;
        float ay = ((float)sy - (float)(SRr+PD)) / (float)SSn;
        float ax = ((float)sx - (float)(SRr+PD)) / (float)SSn;
        sh.dist[tid] = sum * (1.0f/256.0f) + SWt * (ay*ay + ax*ax);
    }
    __syncthreads();
    if (tid < 32) {
        unsigned long long key = ~0ULL;
        for (int k = tid; k < SSC*SSC; k += 32) {
            int py = k / SSC, px = k - (k/SSC)*SSC;
            float v = sh.dist[(py+PD)*SSn + px + PD];
            key = umin64(key, ((unsigned long long)__float_as_uint(v) << 32) | (unsigned)k);
        }
        #pragma unroll
        for (int o = 16; o > 0; o >>= 1)
            key = umin64(key, __shfl_down_sync(0xffffffffu, key, o));
        if (tid == 0) {
            int bk = (int)(key & 0xffffffffu);
            float best = __uint_as_float((unsigned)(key >> 32));
            int py = bk / SSC, px = bk - (bk/SSC)*SSC;
            float r[9];
            #pragma unroll
            for (int dy = 0; dy < 3; dy++)
                #pragma unroll
                for (int dx = 0; dx < 3; dx++)
                    r[dy*3+dx] = sh.dist[(py+PD-1+dy)*SSn + (px+PD-1+dx)];

            float a11 = (  r[0]-2.f*r[1]+r[2] + 2.f*r[3]-4.f*r[4]+2.f*r[5] +   r[6]-2.f*r[7]+r[8]) * 0.25f;
            float a22 = (  r[0]+2.f*r[1]+r[2] - 2.f*r[3]-4.f*r[4]-2.f*r[5] +   r[6]+2.f*r[7]+r[8]) * 0.25f;
            float a12 = (  r[0]        -r[2]                               -   r[6]         +r[8]) * 0.25f;
            float b1  = ( -r[0]        +r[2] - 2.f*r[3]        +2.f*r[5]   -   r[6]         +r[8]) * 0.125f;
            float b2  = ( -r[0]-2.f*r[1]-r[2]                              +   r[6]+2.f*r[7]+r[8]) * 0.125f;
            a11 = fmaxf(a11, 0.f);
            a22 = fmaxf(a22, 0.f);
            float det  = a11*a22 - a12*a12;
            float a12z = (det < 0.f) ? 0.f : a12;
            float mux  = -(a22*b1 - a12z*b2) / det;
            float muy  = -(a11*b2 - a12z*b1) / det;
            float mlen = sqrtf(muy*muy + mux*mux);
            float dxs  = (mlen < 1.f) ? mux : 0.f;   // NaN/Inf -> 0, matches jnp.where
            float dys  = (mlen < 1.f) ? muy : 0.f;

            float offy = sh.init[buf][0] + (float)(py - SRr) + dys;
            float offx = sh.init[buf][1] + (float)(px - SRr) + dxs;
            if (out_off) { out_off[0] = offy; out_off[1] = offx; }
            sh.res[0] = offy; sh.res[1] = offx; sh.res[2] = best;
        }
    }
}

// one alignment level: cp.async double-buffered tile loop
__device__ void step_level(StepSh& sh, int G, int nTiles,
                           const float* __restrict__ src, const float* __restrict__ dst,
                           int H, int nthLog,
                           const float* __restrict__ prev_off, int pnthLog,
                           float* __restrict__ out_off, float* __restrict__ out_pix)
{
    if ((int)blockIdx.x >= nTiles) return;
    const int tid = threadIdx.x;

    issue_load(sh, 0, blockIdx.x, src, dst, H, nthLog, prev_off, pnthLog);
    cp_commit();

    int p = 0;
    for (int t = blockIdx.x; t < nTiles; t += G, p ^= 1) {
        if (t + G < nTiles) {
            issue_load(sh, p ^ 1, t + G, src, dst, H, nthLog, prev_off, pnthLog);
            cp_commit();
            cp_wait<1>();     // group for current tile done (FIFO)
        } else {
            cp_wait<0>();
        }
        __syncthreads();                                   // buf[p] visible
        if (tid < NMSE) mse_tile(sh, p);
        __syncthreads();                                   // part ready
        post_tile(sh, p, out_off ? out_off + (size_t)t*2 : nullptr);
        if (out_pix) {
            __syncthreads();                               // res ready
            const int msk = (1 << nthLog) - 1;
            const int tx = t & msk, ty = (t >> nthLog) & msk, nb = t >> (2*nthLog);
            float2 ov = make_float2(sh.res[0], sh.res[1]);
            int i = tid >> 4, j = tid & 15;
            int y = ty*TSZ + i, x = tx*TSZ + j;
            size_t pix = ((size_t)nb * H + y) * H + x;
            reinterpret_cast<float2*>(out_pix)[pix] = ov;
            out_pix[(size_t)NB * H * H * 2 + pix] = sh.res[2];
        }
    }
}

// ---------------- persistent mega-kernel ------------------------------------
__global__ void __launch_bounds__(256)
align_kernel(const float* __restrict__ src, const float* __restrict__ dst,
             float* __restrict__ out, int G)
{
    __shared__ ShMem sh;
    unsigned local_sense = 0;

    for (int vb = blockIdx.x; vb < 8*64; vb += G)
        pyr_block(sh.py, vb, src, dst);
    grid_barrier(G, local_sense);

    step_level(sh.st, G, NB*4*4,   g_ps3, g_pd3,  64, 2, nullptr, 0, g_offA, nullptr);
    grid_barrier(G, local_sense);

    step_level(sh.st, G, NB*8*8,   g_ps2, g_pd2, 128, 3, g_offA,  2, g_offB, nullptr);
    grid_barrier(G, local_sense);

    step_level(sh.st, G, NB*16*16, g_ps1, g_pd1, 256, 4, g_offB,  3, g_offA, nullptr);
    grid_barrier(G, local_sense);

    step_level(sh.st, G, NB*32*32, src,   dst,   512, 5, g_offA,  4, nullptr, out);
}

// ---------------- launch ---------------------------------------------------
extern "C" void kernel_launch(void* const* d_in, const int* in_sizes, int n_in,
                              void* d_out, int out_size)
{
    const float* src = (const float*)d_in[0];
    const float* dst = (const float*)d_in[1];
    float* out = (float*)d_out;

    static int G = 0;
    if (G == 0) {
        int nsm = 0, bpm = 0;
        cudaDeviceGetAttribute(&nsm, cudaDevAttrMultiProcessorCount, 0);
        cudaOccupancyMaxActiveBlocksPerMultiprocessor(&bpm, align_kernel, 256, 0);
        if (bpm < 1) bpm = 1;
        G = nsm * bpm;
    }

    align_kernel<<<G, 256>>>(src, dst, out, G);
}